// round 1
// baseline (speedup 1.0000x reference)
#include <cuda_runtime.h>
#include <cuda_bf16.h>
#include <cstdint>

// Problem constants
#define BATCH 8
#define CCH   256
#define SPA   16384            // H*W = 128*128
#define HEADS 2
#define HK    128

// ---------------- scratch (static device globals; no allocations) ----------------
__device__ float g_mean[CCH];
__device__ float g_rstd[CCH];
__device__ float g_wf[768 * 256];      // fused BN-folded weights [k;q;v]
__device__ float g_bf[768];            // fused biases
__device__ float g_k[BATCH * CCH * SPA];      // 134 MB
__device__ float g_q[BATCH * CCH * SPA];      // 134 MB
__device__ float g_v[BATCH * CCH * SPA];      // 134 MB
__device__ float g_out2[BATCH * CCH * SPA];   // 134 MB
__device__ float g_ctx_part[16 * 16 * 128 * 128];  // 16 bn-pairs x 16 splits, 16 MB
__device__ float g_context[16 * 128 * 128];        // [b*2+n][kc][vc]
__device__ float g_ctx[BATCH * 128 * 128];         // combined over heads
__device__ float g_pooled[16];
__device__ float g_gate[16];

// ---------------- K1: BatchNorm statistics -----------------------------------
__global__ void k_bnstats(const float* __restrict__ x) {
    const int c = blockIdx.x;
    const int tid = threadIdx.x;
    float s = 0.f, s2 = 0.f;
    for (int b = 0; b < BATCH; ++b) {
        const float4* p = (const float4*)(x + ((size_t)(b * CCH + c) << 14));
        for (int i = tid; i < SPA / 4; i += 256) {
            float4 v = p[i];
            s  += v.x + v.y + v.z + v.w;
            s2 += v.x * v.x + v.y * v.y + v.z * v.z + v.w * v.w;
        }
    }
    __shared__ float sa[256], sb[256];
    sa[tid] = s; sb[tid] = s2;
    __syncthreads();
    for (int st = 128; st > 0; st >>= 1) {
        if (tid < st) { sa[tid] += sa[tid + st]; sb[tid] += sb[tid + st]; }
        __syncthreads();
    }
    if (tid == 0) {
        const float inv_n = 1.f / (float)(BATCH * SPA);
        float mean = sa[0] * inv_n;
        float var  = sb[0] * inv_n - mean * mean;
        g_mean[c] = mean;
        g_rstd[c] = rsqrtf(var + 1e-5f);
    }
}

// ---------------- K2: fold BN into kqv weights -------------------------------
__global__ void k_fuseW(const float* __restrict__ wk, const float* __restrict__ bk,
                        const float* __restrict__ wq, const float* __restrict__ bq,
                        const float* __restrict__ wv, const float* __restrict__ bv,
                        const float* __restrict__ gamma, const float* __restrict__ beta) {
    int o = blockIdx.x * blockDim.x + threadIdx.x;
    if (o >= 768) return;
    const float* W; const float* bias; int r;
    if (o < 256)      { W = wk; bias = bk; r = o; }
    else if (o < 512) { W = wq; bias = bq; r = o - 256; }
    else              { W = wv; bias = bv; r = o - 512; }
    float bacc = bias[r];
    for (int c = 0; c < 256; ++c) {
        float a = g_rstd[c] * gamma[c];
        float d = beta[c] - g_mean[c] * a;
        float w = W[r * 256 + c];
        g_wf[o * 256 + c] = w * a;
        bacc += w * d;
    }
    g_bf[o] = bacc;
}

// ---------------- K3: fused kqv GEMM  [768x256] @ [256 x 131072] -------------
__global__ __launch_bounds__(256) void k_gemm_kqv(const float* __restrict__ x) {
    __shared__ float As[8][128];
    __shared__ float Bs[8][128];
    const int tid = threadIdx.x;
    const int tx = tid & 15, ty = tid >> 4;
    const int bx = blockIdx.x, by = blockIdx.y;
    const int b  = bx >> 7;                 // 128 column-tiles per batch
    const int s0 = (bx & 127) << 7;
    const int m0 = by << 7;
    const float* Bbase = x + ((size_t)b * CCH) * SPA;
    const int am = tid >> 1;                // A: row within tile
    const int ak = (tid & 1) << 2;          // A: k offset (0 or 4)
    const int br = tid >> 5;                // B: k row 0..7
    const int bc = (tid & 31) << 2;         // B: col offset
    float acc[8][8] = {};
    for (int kk = 0; kk < 256; kk += 8) {
        float4 av = *(const float4*)(g_wf + (m0 + am) * 256 + kk + ak);
        float4 bv = *(const float4*)(Bbase + (size_t)(kk + br) * SPA + s0 + bc);
        As[ak + 0][am] = av.x; As[ak + 1][am] = av.y;
        As[ak + 2][am] = av.z; As[ak + 3][am] = av.w;
        *(float4*)&Bs[br][bc] = bv;
        __syncthreads();
#pragma unroll
        for (int p = 0; p < 8; ++p) {
            float a[8], bb[8];
#pragma unroll
            for (int i = 0; i < 8; ++i) a[i]  = As[p][(ty << 3) + i];
#pragma unroll
            for (int j = 0; j < 8; ++j) bb[j] = Bs[p][(tx << 3) + j];
#pragma unroll
            for (int i = 0; i < 8; ++i)
#pragma unroll
                for (int j = 0; j < 8; ++j) acc[i][j] += a[i] * bb[j];
        }
        __syncthreads();
    }
    float* dst; int rbase;
    if (m0 < 256)      { dst = g_k; rbase = m0; }
    else if (m0 < 512) { dst = g_q; rbase = m0 - 256; }
    else               { dst = g_v; rbase = m0 - 512; }
#pragma unroll
    for (int i = 0; i < 8; ++i) {
        int o = m0 + (ty << 3) + i;
        int r = rbase + (ty << 3) + i;
        float bias = g_bf[o];
        float* out = dst + (size_t)(b * CCH + r) * SPA + s0 + (tx << 3);
        float4 v0 = make_float4(acc[i][0] + bias, acc[i][1] + bias,
                                acc[i][2] + bias, acc[i][3] + bias);
        float4 v1 = make_float4(acc[i][4] + bias, acc[i][5] + bias,
                                acc[i][6] + bias, acc[i][7] + bias);
        *(float4*)out = v0;
        *(float4*)(out + 4) = v1;
    }
}

// ---------------- K4: k softmax over spatial dim (row of 16384) --------------
__global__ __launch_bounds__(256) void k_ksoftmax() {
    const size_t base = (size_t)blockIdx.x << 14;
    float4* p = (float4*)(g_k + base);
    const int tid = threadIdx.x;
    float4 v[16];
    float m = -1e30f;
#pragma unroll
    for (int i = 0; i < 16; ++i) {
        v[i] = p[tid + (i << 8)];
        m = fmaxf(m, fmaxf(fmaxf(v[i].x, v[i].y), fmaxf(v[i].z, v[i].w)));
    }
    __shared__ float sm[256];
    sm[tid] = m; __syncthreads();
    for (int st = 128; st > 0; st >>= 1) {
        if (tid < st) sm[tid] = fmaxf(sm[tid], sm[tid + st]);
        __syncthreads();
    }
    const float rowm = sm[0];
    __syncthreads();
    float l = 0.f;
#pragma unroll
    for (int i = 0; i < 16; ++i)
        l += __expf(v[i].x - rowm) + __expf(v[i].y - rowm)
           + __expf(v[i].z - rowm) + __expf(v[i].w - rowm);
    sm[tid] = l; __syncthreads();
    for (int st = 128; st > 0; st >>= 1) {
        if (tid < st) sm[tid] += sm[tid + st];
        __syncthreads();
    }
    const float inv = 1.f / sm[0];
#pragma unroll
    for (int i = 0; i < 16; ++i) {
        float4 o;
        o.x = __expf(v[i].x - rowm) * inv;
        o.y = __expf(v[i].y - rowm) * inv;
        o.z = __expf(v[i].z - rowm) * inv;
        o.w = __expf(v[i].w - rowm) * inv;
        p[tid + (i << 8)] = o;
    }
}

// ---------------- K5: q softmax over channel (128 per head, strided) ---------
__global__ void k_qsoftmax() {
    int j = blockIdx.x * 256 + threadIdx.x;         // 0..262143 columns
    int b = j >> 15;
    int n = (j >> 14) & 1;
    int s = j & 16383;
    float* col = g_q + ((size_t)(b * CCH + n * HK)) * SPA + s;
    float m = -1e30f, l = 0.f;
    for (int kc = 0; kc < HK; ++kc) {
        float xv = col[(size_t)kc * SPA];
        float nm = fmaxf(m, xv);
        l = l * __expf(m - nm) + __expf(xv - nm);
        m = nm;
    }
    float inv = 1.f / l;
    for (int kc = 0; kc < HK; ++kc) {
        float xv = col[(size_t)kc * SPA];
        col[(size_t)kc * SPA] = __expf(xv - m) * inv;
    }
}

// ---------------- K6: context partials  k_sm @ v^T (split-S) -----------------
__global__ __launch_bounds__(256) void k_context() {
    __shared__ float As[8][128];
    __shared__ float Bs[8][128];
    const int tid = threadIdx.x;
    const int tx = tid & 15, ty = tid >> 4;
    const int split = blockIdx.x;     // 0..15
    const int bn = blockIdx.y;        // 0..15 (b*2+n)
    const float* Kb = g_k + ((size_t)bn * HK) * SPA;
    const float* Vb = g_v + ((size_t)bn * HK) * SPA;
    const int sb0 = split * 1024;
    const int am = tid >> 1;
    const int ak = (tid & 1) << 2;
    float acc[8][8] = {};
    for (int kk = 0; kk < 1024; kk += 8) {
        float4 av = *(const float4*)(Kb + (size_t)am * SPA + sb0 + kk + ak);
        float4 bv = *(const float4*)(Vb + (size_t)am * SPA + sb0 + kk + ak);
        As[ak + 0][am] = av.x; As[ak + 1][am] = av.y;
        As[ak + 2][am] = av.z; As[ak + 3][am] = av.w;
        Bs[ak + 0][am] = bv.x; Bs[ak + 1][am] = bv.y;
        Bs[ak + 2][am] = bv.z; Bs[ak + 3][am] = bv.w;
        __syncthreads();
#pragma unroll
        for (int p = 0; p < 8; ++p) {
            float a[8], bb[8];
#pragma unroll
            for (int i = 0; i < 8; ++i) a[i]  = As[p][(ty << 3) + i];
#pragma unroll
            for (int j = 0; j < 8; ++j) bb[j] = Bs[p][(tx << 3) + j];
#pragma unroll
            for (int i = 0; i < 8; ++i)
#pragma unroll
                for (int j = 0; j < 8; ++j) acc[i][j] += a[i] * bb[j];
        }
        __syncthreads();
    }
    float* outp = g_ctx_part + ((size_t)(bn * 16 + split)) * 16384;
#pragma unroll
    for (int i = 0; i < 8; ++i) {
        float* o = outp + ((ty << 3) + i) * 128 + (tx << 3);
        *(float4*)o       = make_float4(acc[i][0], acc[i][1], acc[i][2], acc[i][3]);
        *(float4*)(o + 4) = make_float4(acc[i][4], acc[i][5], acc[i][6], acc[i][7]);
    }
}

// ---------------- K7: reduce partials + pooled mean ---------------------------
__global__ void k_reduce_ctx() {
    const int bn = blockIdx.x;
    const int tid = threadIdx.x;
    float acc = 0.f;
    for (int e = tid; e < 16384; e += 256) {
        float s = 0.f;
#pragma unroll
        for (int p = 0; p < 16; ++p)
            s += g_ctx_part[((size_t)(bn * 16 + p)) * 16384 + e];
        g_context[((size_t)bn << 14) + e] = s;
        acc += s;
    }
    __shared__ float sm[256];
    sm[tid] = acc; __syncthreads();
    for (int st = 128; st > 0; st >>= 1) {
        if (tid < st) sm[tid] += sm[tid + st];
        __syncthreads();
    }
    if (tid == 0) g_pooled[bn] = sm[0] * (1.f / 16384.f);
}

// ---------------- K8: SE gate (fc1 -> relu -> fc2 -> sigmoid) ----------------
__global__ void k_gate(const float* __restrict__ w_fc1, const float* __restrict__ b_fc1,
                       const float* __restrict__ w_fc2, const float* __restrict__ b_fc2) {
    int b = threadIdx.x;
    if (b >= BATCH) return;
    float p0 = g_pooled[b * 2], p1 = g_pooled[b * 2 + 1];
    float h0 = fmaxf(0.f, p0 * w_fc1[0] + p1 * w_fc1[1] + b_fc1[0]);
    float h1 = fmaxf(0.f, p0 * w_fc1[2] + p1 * w_fc1[3] + b_fc1[1]);
    float z0 = h0 * w_fc2[0] + h1 * w_fc2[1] + b_fc2[0];
    float z1 = h0 * w_fc2[2] + h1 * w_fc2[3] + b_fc2[1];
    g_gate[b * 2]     = 1.f / (1.f + __expf(-z0));
    g_gate[b * 2 + 1] = 1.f / (1.f + __expf(-z1));
}

// ---------------- K9: combine heads: w_se . (gate*context) + b_se ------------
__global__ void k_combine(const float* __restrict__ w_se, const float* __restrict__ b_se) {
    int idx = blockIdx.x * 256 + threadIdx.x;   // < 8*16384
    int b = idx >> 14;
    int e = idx & 16383;
    float v = w_se[0] * g_gate[b * 2]     * g_context[((size_t)(b * 2))     * 16384 + e]
            + w_se[1] * g_gate[b * 2 + 1] * g_context[((size_t)(b * 2 + 1)) * 16384 + e]
            + b_se[0];
    g_ctx[idx] = v;
}

// ---------------- K10: second pass  ctx^T @ q_sm per (b,head) ----------------
__global__ __launch_bounds__(256) void k_attn2() {
    __shared__ float As[8][128];
    __shared__ float Bs[8][128];
    const int tid = threadIdx.x;
    const int tx = tid & 15, ty = tid >> 4;
    const int st = blockIdx.x;      // 0..127  s-tiles
    const int bn = blockIdx.y;      // 0..15
    const int b  = bn >> 1;
    const int s0 = st << 7;
    const float* A  = g_ctx + (size_t)b * 16384;              // [kc][vc], vc contiguous
    const float* Bq = g_q + ((size_t)(bn * HK)) * SPA;
    const int ar = tid >> 5;
    const int ac = (tid & 31) << 2;
    float acc[8][8] = {};
    for (int kk = 0; kk < 128; kk += 8) {
        float4 av = *(const float4*)(A + (kk + ar) * 128 + ac);
        float4 bv = *(const float4*)(Bq + (size_t)(kk + ar) * SPA + s0 + ac);
        *(float4*)&As[ar][ac] = av;
        *(float4*)&Bs[ar][ac] = bv;
        __syncthreads();
#pragma unroll
        for (int p = 0; p < 8; ++p) {
            float a[8], bb[8];
#pragma unroll
            for (int i = 0; i < 8; ++i) a[i]  = As[p][(ty << 3) + i];   // vc
#pragma unroll
            for (int j = 0; j < 8; ++j) bb[j] = Bs[p][(tx << 3) + j];   // s
#pragma unroll
            for (int i = 0; i < 8; ++i)
#pragma unroll
                for (int j = 0; j < 8; ++j) acc[i][j] += a[i] * bb[j];
        }
        __syncthreads();
    }
#pragma unroll
    for (int i = 0; i < 8; ++i) {
        float* out = g_out2 + ((size_t)(bn * HK + (ty << 3) + i)) * SPA + s0 + (tx << 3);
        *(float4*)out       = make_float4(acc[i][0], acc[i][1], acc[i][2], acc[i][3]);
        *(float4*)(out + 4) = make_float4(acc[i][4], acc[i][5], acc[i][6], acc[i][7]);
    }
}

// ---------------- K11: final GEMM  w_rep @ out2 + b_rep -----------------------
__global__ __launch_bounds__(256) void k_final(const float* __restrict__ w_rep,
                                               const float* __restrict__ b_rep,
                                               float* __restrict__ out) {
    __shared__ float As[8][128];
    __shared__ float Bs[8][128];
    const int tid = threadIdx.x;
    const int tx = tid & 15, ty = tid >> 4;
    const int bx = blockIdx.x, by = blockIdx.y;
    const int b  = bx >> 7;
    const int s0 = (bx & 127) << 7;
    const int m0 = by << 7;
    const float* Bbase = g_out2 + ((size_t)b * CCH) * SPA;
    const int am = tid >> 1;
    const int ak = (tid & 1) << 2;
    const int br = tid >> 5;
    const int bc = (tid & 31) << 2;
    float acc[8][8] = {};
    for (int kk = 0; kk < 256; kk += 8) {
        float4 av = *(const float4*)(w_rep + (m0 + am) * 256 + kk + ak);
        float4 bv = *(const float4*)(Bbase + (size_t)(kk + br) * SPA + s0 + bc);
        As[ak + 0][am] = av.x; As[ak + 1][am] = av.y;
        As[ak + 2][am] = av.z; As[ak + 3][am] = av.w;
        *(float4*)&Bs[br][bc] = bv;
        __syncthreads();
#pragma unroll
        for (int p = 0; p < 8; ++p) {
            float a[8], bb[8];
#pragma unroll
            for (int i = 0; i < 8; ++i) a[i]  = As[p][(ty << 3) + i];
#pragma unroll
            for (int j = 0; j < 8; ++j) bb[j] = Bs[p][(tx << 3) + j];
#pragma unroll
            for (int i = 0; i < 8; ++i)
#pragma unroll
                for (int j = 0; j < 8; ++j) acc[i][j] += a[i] * bb[j];
        }
        __syncthreads();
    }
#pragma unroll
    for (int i = 0; i < 8; ++i) {
        int o = m0 + (ty << 3) + i;
        float bias = b_rep[o];
        float* outp = out + (size_t)(b * CCH + o) * SPA + s0 + (tx << 3);
        float4 v0 = make_float4(acc[i][0] + bias, acc[i][1] + bias,
                                acc[i][2] + bias, acc[i][3] + bias);
        float4 v1 = make_float4(acc[i][4] + bias, acc[i][5] + bias,
                                acc[i][6] + bias, acc[i][7] + bias);
        *(float4*)outp = v0;
        *(float4*)(outp + 4) = v1;
    }
}

// ---------------- launch -------------------------------------------------------
extern "C" void kernel_launch(void* const* d_in, const int* in_sizes, int n_in,
                              void* d_out, int out_size) {
    const float* x     = (const float*)d_in[0];
    const float* gamma = (const float*)d_in[1];
    const float* beta  = (const float*)d_in[2];
    const float* wk    = (const float*)d_in[3];
    const float* bk    = (const float*)d_in[4];
    const float* wq    = (const float*)d_in[5];
    const float* bq    = (const float*)d_in[6];
    const float* wv    = (const float*)d_in[7];
    const float* bv    = (const float*)d_in[8];
    const float* w_fc1 = (const float*)d_in[9];
    const float* b_fc1 = (const float*)d_in[10];
    const float* w_fc2 = (const float*)d_in[11];
    const float* b_fc2 = (const float*)d_in[12];
    const float* w_se  = (const float*)d_in[13];
    const float* b_se  = (const float*)d_in[14];
    const float* w_rep = (const float*)d_in[15];
    const float* b_rep = (const float*)d_in[16];
    float* out = (float*)d_out;

    k_bnstats<<<256, 256>>>(x);
    k_fuseW<<<3, 256>>>(wk, bk, wq, bq, wv, bv, gamma, beta);
    k_gemm_kqv<<<dim3(1024, 6), 256>>>(x);
    k_ksoftmax<<<2048, 256>>>();
    k_qsoftmax<<<1024, 256>>>();
    k_context<<<dim3(16, 16), 256>>>();
    k_reduce_ctx<<<16, 256>>>();
    k_gate<<<1, 32>>>(w_fc1, b_fc1, w_fc2, b_fc2);
    k_combine<<<512, 256>>>(w_se, b_se);
    k_attn2<<<dim3(128, 16), 256>>>();
    k_final<<<dim3(1024, 2), 256>>>(w_rep, b_rep, out);
}

// round 2
// speedup vs baseline: 1.9656x; 1.9656x over previous
#include <cuda_runtime.h>
#include <cuda_bf16.h>
#include <cstdint>

#define BATCH 8
#define CCH   256
#define SPA   16384
#define HEADS 2
#define HK    128

// ---------------- scratch ----------------
__device__ float g_mean[CCH];
__device__ float g_rstd[CCH];
__device__ float g_wf[768 * 256];
__device__ float g_bf[768];
__device__ float g_k[BATCH * CCH * SPA];
__device__ float g_q[BATCH * CCH * SPA];
__device__ float g_v[BATCH * CCH * SPA];
__device__ float g_out2[BATCH * CCH * SPA];
__device__ float g_ctx_part[16 * 16 * 128 * 128];
__device__ float g_context[16 * 128 * 128];
__device__ float g_ctx[BATCH * 128 * 128];
__device__ float g_pooled[16];
__device__ float g_gate[16];

// ---------------- tf32 mma helpers ----------------
__device__ __forceinline__ uint32_t f2tf32(float f) {
    uint32_t r;
    asm("cvt.rna.tf32.f32 %0, %1;" : "=r"(r) : "f"(f));
    return r;
}

__device__ __forceinline__ void mma_tf32(float c[4], const uint32_t a[4], const uint32_t b[2]) {
    asm volatile(
        "mma.sync.aligned.m16n8k8.row.col.f32.tf32.tf32.f32 "
        "{%0,%1,%2,%3}, {%4,%5,%6,%7}, {%8,%9}, {%0,%1,%2,%3};"
        : "+f"(c[0]), "+f"(c[1]), "+f"(c[2]), "+f"(c[3])
        : "r"(a[0]), "r"(a[1]), "r"(a[2]), "r"(a[3]), "r"(b[0]), "r"(b[1]));
}

#define ASTRIDE 36
#define BSTRIDE 132

// One k8 step over a 64x32 warp tile: 4 M-subtiles x 4 N-subtiles.
__device__ __forceinline__ void mma_tile_step(
    const uint32_t* __restrict__ As, const uint32_t* __restrict__ Bs,
    int mw, int nw, int g, int tig, int kk, float (&acc)[4][4][4])
{
    uint32_t a[4][4], b[4][2];
#pragma unroll
    for (int i = 0; i < 4; ++i) {
        const uint32_t* A0 = As + (mw + i * 16 + g) * ASTRIDE + kk;
        const uint32_t* A1 = A0 + 8 * ASTRIDE;
        a[i][0] = A0[tig];     a[i][1] = A1[tig];
        a[i][2] = A0[tig + 4]; a[i][3] = A1[tig + 4];
    }
#pragma unroll
    for (int j = 0; j < 4; ++j) {
        int cb = nw + j * 8 + g;
        b[j][0] = Bs[(kk + tig) * BSTRIDE + cb];
        b[j][1] = Bs[(kk + tig + 4) * BSTRIDE + cb];
    }
#pragma unroll
    for (int i = 0; i < 4; ++i)
#pragma unroll
        for (int j = 0; j < 4; ++j)
            mma_tf32(acc[i][j], a[i], b[j]);
}

// ---------------- K1: BatchNorm statistics ----------------
__global__ void k_bnstats(const float* __restrict__ x) {
    const int c = blockIdx.x;
    const int tid = threadIdx.x;
    float s = 0.f, s2 = 0.f;
    for (int b = 0; b < BATCH; ++b) {
        const float4* p = (const float4*)(x + ((size_t)(b * CCH + c) << 14));
        for (int i = tid; i < SPA / 4; i += 256) {
            float4 v = p[i];
            s  += v.x + v.y + v.z + v.w;
            s2 += v.x * v.x + v.y * v.y + v.z * v.z + v.w * v.w;
        }
    }
    __shared__ float sa[256], sb[256];
    sa[tid] = s; sb[tid] = s2;
    __syncthreads();
    for (int st = 128; st > 0; st >>= 1) {
        if (tid < st) { sa[tid] += sa[tid + st]; sb[tid] += sb[tid + st]; }
        __syncthreads();
    }
    if (tid == 0) {
        const float inv_n = 1.f / (float)(BATCH * SPA);
        float mean = sa[0] * inv_n;
        float var  = sb[0] * inv_n - mean * mean;
        g_mean[c] = mean;
        g_rstd[c] = rsqrtf(var + 1e-5f);
    }
}

// ---------------- K2: fold BN into kqv weights ----------------
__global__ void k_fuseW(const float* __restrict__ wk, const float* __restrict__ bk,
                        const float* __restrict__ wq, const float* __restrict__ bq,
                        const float* __restrict__ wv, const float* __restrict__ bv,
                        const float* __restrict__ gamma, const float* __restrict__ beta) {
    int o = blockIdx.x * blockDim.x + threadIdx.x;
    if (o >= 768) return;
    const float* W; const float* bias; int r;
    if (o < 256)      { W = wk; bias = bk; r = o; }
    else if (o < 512) { W = wq; bias = bq; r = o - 256; }
    else              { W = wv; bias = bv; r = o - 512; }
    float bacc = bias[r];
    for (int c = 0; c < 256; ++c) {
        float a = g_rstd[c] * gamma[c];
        float d = beta[c] - g_mean[c] * a;
        float w = W[r * 256 + c];
        g_wf[o * 256 + c] = w * a;
        bacc += w * d;
    }
    g_bf[o] = bacc;
}

// ---------------- K3: fused kqv GEMM (tf32 tensor cores) ----------------
// C[768 x 8*16384] = g_wf[768,256] @ x[b][256, 16384]
__global__ __launch_bounds__(256) void k_gemm_kqv(const float* __restrict__ x) {
    __shared__ uint32_t As[128 * ASTRIDE];
    __shared__ uint32_t Bs[32 * BSTRIDE];
    const int tid = threadIdx.x;
    const int lane = tid & 31;
    const int wid = tid >> 5;
    const int g = lane >> 2, tig = lane & 3;
    const int mw = (wid & 1) * 64, nw = (wid >> 1) * 32;

    const int bx = blockIdx.x;
    const int b  = bx >> 7;
    const int s0 = (bx & 127) << 7;
    const int m0 = blockIdx.y << 7;
    const float* Bbase = x + ((size_t)b * CCH) * SPA;

    // staging index maps
    const int ar = tid >> 1;            // A row 0..127
    const int ac = (tid & 1) << 4;      // A col 0/16
    const int brr = tid >> 3;           // B row 0..31
    const int bcc = (tid & 7) << 4;     // B col 0..112

    float acc[4][4][4] = {};
    float4 pa[4], pb[4];

    // stage 0
#pragma unroll
    for (int f = 0; f < 4; ++f) {
        pa[f] = *(const float4*)(g_wf + (m0 + ar) * 256 + ac + f * 4);
        pb[f] = *(const float4*)(Bbase + (size_t)brr * SPA + s0 + bcc + f * 4);
    }
#pragma unroll
    for (int f = 0; f < 4; ++f) {
        uint32_t* pA = As + ar * ASTRIDE + ac + f * 4;
        pA[0] = f2tf32(pa[f].x); pA[1] = f2tf32(pa[f].y);
        pA[2] = f2tf32(pa[f].z); pA[3] = f2tf32(pa[f].w);
        uint32_t* pB = Bs + brr * BSTRIDE + bcc + f * 4;
        pB[0] = f2tf32(pb[f].x); pB[1] = f2tf32(pb[f].y);
        pB[2] = f2tf32(pb[f].z); pB[3] = f2tf32(pb[f].w);
    }
    __syncthreads();

    for (int ks = 0; ks < 256; ks += 32) {
        const bool more = (ks + 32) < 256;
        if (more) {
#pragma unroll
            for (int f = 0; f < 4; ++f) {
                pa[f] = *(const float4*)(g_wf + (m0 + ar) * 256 + ks + 32 + ac + f * 4);
                pb[f] = *(const float4*)(Bbase + (size_t)(ks + 32 + brr) * SPA + s0 + bcc + f * 4);
            }
        }
#pragma unroll
        for (int kk = 0; kk < 32; kk += 8)
            mma_tile_step(As, Bs, mw, nw, g, tig, kk, acc);
        __syncthreads();
        if (more) {
#pragma unroll
            for (int f = 0; f < 4; ++f) {
                uint32_t* pA = As + ar * ASTRIDE + ac + f * 4;
                pA[0] = f2tf32(pa[f].x); pA[1] = f2tf32(pa[f].y);
                pA[2] = f2tf32(pa[f].z); pA[3] = f2tf32(pa[f].w);
                uint32_t* pB = Bs + brr * BSTRIDE + bcc + f * 4;
                pB[0] = f2tf32(pb[f].x); pB[1] = f2tf32(pb[f].y);
                pB[2] = f2tf32(pb[f].z); pB[3] = f2tf32(pb[f].w);
            }
            __syncthreads();
        }
    }

    float* dst; int rbase;
    if (m0 < 256)      { dst = g_k; rbase = m0; }
    else if (m0 < 512) { dst = g_q; rbase = m0 - 256; }
    else               { dst = g_v; rbase = m0 - 512; }

#pragma unroll
    for (int i = 0; i < 4; ++i) {
        int row0 = mw + i * 16 + g;
        float bias0 = g_bf[m0 + row0];
        float bias1 = g_bf[m0 + row0 + 8];
#pragma unroll
        for (int j = 0; j < 4; ++j) {
            int col = s0 + nw + j * 8 + tig * 2;
            float* o0 = dst + (size_t)(b * CCH + rbase + row0) * SPA + col;
            float* o1 = o0 + 8 * SPA;
            *(float2*)o0 = make_float2(acc[i][j][0] + bias0, acc[i][j][1] + bias0);
            *(float2*)o1 = make_float2(acc[i][j][2] + bias1, acc[i][j][3] + bias1);
        }
    }
}

// ---------------- K4: k softmax over spatial ----------------
__global__ __launch_bounds__(256) void k_ksoftmax() {
    const size_t base = (size_t)blockIdx.x << 14;
    float4* p = (float4*)(g_k + base);
    const int tid = threadIdx.x;
    float4 v[16];
    float m = -1e30f;
#pragma unroll
    for (int i = 0; i < 16; ++i) {
        v[i] = p[tid + (i << 8)];
        m = fmaxf(m, fmaxf(fmaxf(v[i].x, v[i].y), fmaxf(v[i].z, v[i].w)));
    }
    __shared__ float sm[256];
    sm[tid] = m; __syncthreads();
    for (int st = 128; st > 0; st >>= 1) {
        if (tid < st) sm[tid] = fmaxf(sm[tid], sm[tid + st]);
        __syncthreads();
    }
    const float rowm = sm[0];
    __syncthreads();
    float l = 0.f;
#pragma unroll
    for (int i = 0; i < 16; ++i)
        l += __expf(v[i].x - rowm) + __expf(v[i].y - rowm)
           + __expf(v[i].z - rowm) + __expf(v[i].w - rowm);
    sm[tid] = l; __syncthreads();
    for (int st = 128; st > 0; st >>= 1) {
        if (tid < st) sm[tid] += sm[tid + st];
        __syncthreads();
    }
    const float inv = 1.f / sm[0];
#pragma unroll
    for (int i = 0; i < 16; ++i) {
        float4 o;
        o.x = __expf(v[i].x - rowm) * inv;
        o.y = __expf(v[i].y - rowm) * inv;
        o.z = __expf(v[i].z - rowm) * inv;
        o.w = __expf(v[i].w - rowm) * inv;
        p[tid + (i << 8)] = o;
    }
}

// ---------------- K5: q softmax over channel ----------------
__global__ void k_qsoftmax() {
    int j = blockIdx.x * 256 + threadIdx.x;
    int b = j >> 15;
    int n = (j >> 14) & 1;
    int s = j & 16383;
    float* col = g_q + ((size_t)(b * CCH + n * HK)) * SPA + s;
    float m = -1e30f, l = 0.f;
    for (int kc = 0; kc < HK; ++kc) {
        float xv = col[(size_t)kc * SPA];
        float nm = fmaxf(m, xv);
        l = l * __expf(m - nm) + __expf(xv - nm);
        m = nm;
    }
    float inv = 1.f / l;
    for (int kc = 0; kc < HK; ++kc) {
        float xv = col[(size_t)kc * SPA];
        col[(size_t)kc * SPA] = __expf(xv - m) * inv;
    }
}

// ---------------- K6: context partials k_sm @ v^T (tf32) ----------------
__global__ __launch_bounds__(256) void k_context() {
    __shared__ uint32_t As[128 * ASTRIDE];
    __shared__ uint32_t Bs[32 * BSTRIDE];
    const int tid = threadIdx.x;
    const int lane = tid & 31;
    const int wid = tid >> 5;
    const int g = lane >> 2, tig = lane & 3;
    const int mw = (wid & 1) * 64, nw = (wid >> 1) * 32;

    const int split = blockIdx.x;
    const int bn = blockIdx.y;
    const float* Kb = g_k + ((size_t)bn * HK) * SPA;
    const float* Vb = g_v + ((size_t)bn * HK) * SPA;
    const int sb0 = split * 1024;

    const int ar = tid >> 1;          // kc row 0..127
    const int ac = (tid & 1) << 4;    // s offset 0/16
    const int vr = tid >> 1;          // vc row 0..127 (transposed into Bs)
    const int vq = (tid & 1) << 4;

    float acc[4][4][4] = {};
    float4 pa[4], pb[4];

#pragma unroll
    for (int f = 0; f < 4; ++f) {
        pa[f] = *(const float4*)(Kb + (size_t)ar * SPA + sb0 + ac + f * 4);
        pb[f] = *(const float4*)(Vb + (size_t)vr * SPA + sb0 + vq + f * 4);
    }
#pragma unroll
    for (int f = 0; f < 4; ++f) {
        uint32_t* pA = As + ar * ASTRIDE + ac + f * 4;
        pA[0] = f2tf32(pa[f].x); pA[1] = f2tf32(pa[f].y);
        pA[2] = f2tf32(pa[f].z); pA[3] = f2tf32(pa[f].w);
        int sbase = vq + f * 4;
        Bs[(sbase + 0) * BSTRIDE + vr] = f2tf32(pb[f].x);
        Bs[(sbase + 1) * BSTRIDE + vr] = f2tf32(pb[f].y);
        Bs[(sbase + 2) * BSTRIDE + vr] = f2tf32(pb[f].z);
        Bs[(sbase + 3) * BSTRIDE + vr] = f2tf32(pb[f].w);
    }
    __syncthreads();

    for (int ks = 0; ks < 1024; ks += 32) {
        const bool more = (ks + 32) < 1024;
        if (more) {
#pragma unroll
            for (int f = 0; f < 4; ++f) {
                pa[f] = *(const float4*)(Kb + (size_t)ar * SPA + sb0 + ks + 32 + ac + f * 4);
                pb[f] = *(const float4*)(Vb + (size_t)vr * SPA + sb0 + ks + 32 + vq + f * 4);
            }
        }
#pragma unroll
        for (int kk = 0; kk < 32; kk += 8)
            mma_tile_step(As, Bs, mw, nw, g, tig, kk, acc);
        __syncthreads();
        if (more) {
#pragma unroll
            for (int f = 0; f < 4; ++f) {
                uint32_t* pA = As + ar * ASTRIDE + ac + f * 4;
                pA[0] = f2tf32(pa[f].x); pA[1] = f2tf32(pa[f].y);
                pA[2] = f2tf32(pa[f].z); pA[3] = f2tf32(pa[f].w);
                int sbase = vq + f * 4;
                Bs[(sbase + 0) * BSTRIDE + vr] = f2tf32(pb[f].x);
                Bs[(sbase + 1) * BSTRIDE + vr] = f2tf32(pb[f].y);
                Bs[(sbase + 2) * BSTRIDE + vr] = f2tf32(pb[f].z);
                Bs[(sbase + 3) * BSTRIDE + vr] = f2tf32(pb[f].w);
            }
            __syncthreads();
        }
    }

    float* outp = g_ctx_part + ((size_t)(bn * 16 + split)) * 16384;
#pragma unroll
    for (int i = 0; i < 4; ++i) {
        int row0 = mw + i * 16 + g;
#pragma unroll
        for (int j = 0; j < 4; ++j) {
            int col = nw + j * 8 + tig * 2;
            float* o0 = outp + row0 * 128 + col;
            float* o1 = o0 + 8 * 128;
            *(float2*)o0 = make_float2(acc[i][j][0], acc[i][j][1]);
            *(float2*)o1 = make_float2(acc[i][j][2], acc[i][j][3]);
        }
    }
}

// ---------------- K7: reduce partials + pooled mean ----------------
__global__ void k_reduce_ctx() {
    const int bn = blockIdx.x;
    const int tid = threadIdx.x;
    float acc = 0.f;
    for (int e = tid; e < 16384; e += 256) {
        float s = 0.f;
#pragma unroll
        for (int p = 0; p < 16; ++p)
            s += g_ctx_part[((size_t)(bn * 16 + p)) * 16384 + e];
        g_context[((size_t)bn << 14) + e] = s;
        acc += s;
    }
    __shared__ float sm[256];
    sm[tid] = acc; __syncthreads();
    for (int st = 128; st > 0; st >>= 1) {
        if (tid < st) sm[tid] += sm[tid + st];
        __syncthreads();
    }
    if (tid == 0) g_pooled[bn] = sm[0] * (1.f / 16384.f);
}

// ---------------- K8: SE gate ----------------
__global__ void k_gate(const float* __restrict__ w_fc1, const float* __restrict__ b_fc1,
                       const float* __restrict__ w_fc2, const float* __restrict__ b_fc2) {
    int b = threadIdx.x;
    if (b >= BATCH) return;
    float p0 = g_pooled[b * 2], p1 = g_pooled[b * 2 + 1];
    float h0 = fmaxf(0.f, p0 * w_fc1[0] + p1 * w_fc1[1] + b_fc1[0]);
    float h1 = fmaxf(0.f, p0 * w_fc1[2] + p1 * w_fc1[3] + b_fc1[1]);
    float z0 = h0 * w_fc2[0] + h1 * w_fc2[1] + b_fc2[0];
    float z1 = h0 * w_fc2[2] + h1 * w_fc2[3] + b_fc2[1];
    g_gate[b * 2]     = 1.f / (1.f + __expf(-z0));
    g_gate[b * 2 + 1] = 1.f / (1.f + __expf(-z1));
}

// ---------------- K9: combine heads ----------------
__global__ void k_combine(const float* __restrict__ w_se, const float* __restrict__ b_se) {
    int idx = blockIdx.x * 256 + threadIdx.x;
    int b = idx >> 14;
    int e = idx & 16383;
    float v = w_se[0] * g_gate[b * 2]     * g_context[((size_t)(b * 2))     * 16384 + e]
            + w_se[1] * g_gate[b * 2 + 1] * g_context[((size_t)(b * 2 + 1)) * 16384 + e]
            + b_se[0];
    g_ctx[idx] = v;
}

// ---------------- K10: second pass ctx^T @ q_sm (tf32) ----------------
__global__ __launch_bounds__(256) void k_attn2() {
    __shared__ uint32_t As[128 * ASTRIDE];
    __shared__ uint32_t Bs[32 * BSTRIDE];
    const int tid = threadIdx.x;
    const int lane = tid & 31;
    const int wid = tid >> 5;
    const int g = lane >> 2, tig = lane & 3;
    const int mw = (wid & 1) * 64, nw = (wid >> 1) * 32;

    const int st = blockIdx.x;
    const int bn = blockIdx.y;
    const int b  = bn >> 1;
    const int s0 = st << 7;
    const float* Actx = g_ctx + (size_t)b * 16384;        // [kc][vc]
    const float* Bq = g_q + ((size_t)(bn * HK)) * SPA;

    const int akc = tid >> 3;         // kc 0..31
    const int avq = (tid & 7) << 4;   // vc 0..112
    const int brr = tid >> 3;         // kc 0..31
    const int bcc = (tid & 7) << 4;   // s offset

    float acc[4][4][4] = {};
    float4 pa[4], pb[4];

#pragma unroll
    for (int f = 0; f < 4; ++f) {
        pa[f] = *(const float4*)(Actx + akc * 128 + avq + f * 4);
        pb[f] = *(const float4*)(Bq + (size_t)brr * SPA + s0 + bcc + f * 4);
    }
#pragma unroll
    for (int f = 0; f < 4; ++f) {
        int vb = avq + f * 4;
        As[(vb + 0) * ASTRIDE + akc] = f2tf32(pa[f].x);
        As[(vb + 1) * ASTRIDE + akc] = f2tf32(pa[f].y);
        As[(vb + 2) * ASTRIDE + akc] = f2tf32(pa[f].z);
        As[(vb + 3) * ASTRIDE + akc] = f2tf32(pa[f].w);
        uint32_t* pB = Bs + brr * BSTRIDE + bcc + f * 4;
        pB[0] = f2tf32(pb[f].x); pB[1] = f2tf32(pb[f].y);
        pB[2] = f2tf32(pb[f].z); pB[3] = f2tf32(pb[f].w);
    }
    __syncthreads();

    for (int ks = 0; ks < 128; ks += 32) {
        const bool more = (ks + 32) < 128;
        if (more) {
#pragma unroll
            for (int f = 0; f < 4; ++f) {
                pa[f] = *(const float4*)(Actx + (ks + 32 + akc) * 128 + avq + f * 4);
                pb[f] = *(const float4*)(Bq + (size_t)(ks + 32 + brr) * SPA + s0 + bcc + f * 4);
            }
        }
#pragma unroll
        for (int kk = 0; kk < 32; kk += 8)
            mma_tile_step(As, Bs, mw, nw, g, tig, kk, acc);
        __syncthreads();
        if (more) {
#pragma unroll
            for (int f = 0; f < 4; ++f) {
                int vb = avq + f * 4;
                As[(vb + 0) * ASTRIDE + akc] = f2tf32(pa[f].x);
                As[(vb + 1) * ASTRIDE + akc] = f2tf32(pa[f].y);
                As[(vb + 2) * ASTRIDE + akc] = f2tf32(pa[f].z);
                As[(vb + 3) * ASTRIDE + akc] = f2tf32(pa[f].w);
                uint32_t* pB = Bs + brr * BSTRIDE + bcc + f * 4;
                pB[0] = f2tf32(pb[f].x); pB[1] = f2tf32(pb[f].y);
                pB[2] = f2tf32(pb[f].z); pB[3] = f2tf32(pb[f].w);
            }
            __syncthreads();
        }
    }

#pragma unroll
    for (int i = 0; i < 4; ++i) {
        int row0 = mw + i * 16 + g;       // vc
#pragma unroll
        for (int j = 0; j < 4; ++j) {
            int col = s0 + nw + j * 8 + tig * 2;
            float* o0 = g_out2 + (size_t)(bn * HK + row0) * SPA + col;
            float* o1 = o0 + (size_t)8 * SPA;
            *(float2*)o0 = make_float2(acc[i][j][0], acc[i][j][1]);
            *(float2*)o1 = make_float2(acc[i][j][2], acc[i][j][3]);
        }
    }
}

// ---------------- K11: final GEMM w_rep @ out2 + b_rep (tf32) ----------------
__global__ __launch_bounds__(256) void k_final(const float* __restrict__ w_rep,
                                               const float* __restrict__ b_rep,
                                               float* __restrict__ out) {
    __shared__ uint32_t As[128 * ASTRIDE];
    __shared__ uint32_t Bs[32 * BSTRIDE];
    const int tid = threadIdx.x;
    const int lane = tid & 31;
    const int wid = tid >> 5;
    const int g = lane >> 2, tig = lane & 3;
    const int mw = (wid & 1) * 64, nw = (wid >> 1) * 32;

    const int bx = blockIdx.x;
    const int b  = bx >> 7;
    const int s0 = (bx & 127) << 7;
    const int m0 = blockIdx.y << 7;
    const float* Bbase = g_out2 + ((size_t)b * CCH) * SPA;

    const int ar = tid >> 1;
    const int ac = (tid & 1) << 4;
    const int brr = tid >> 3;
    const int bcc = (tid & 7) << 4;

    float acc[4][4][4] = {};
    float4 pa[4], pb[4];

#pragma unroll
    for (int f = 0; f < 4; ++f) {
        pa[f] = *(const float4*)(w_rep + (m0 + ar) * 256 + ac + f * 4);
        pb[f] = *(const float4*)(Bbase + (size_t)brr * SPA + s0 + bcc + f * 4);
    }
#pragma unroll
    for (int f = 0; f < 4; ++f) {
        uint32_t* pA = As + ar * ASTRIDE + ac + f * 4;
        pA[0] = f2tf32(pa[f].x); pA[1] = f2tf32(pa[f].y);
        pA[2] = f2tf32(pa[f].z); pA[3] = f2tf32(pa[f].w);
        uint32_t* pB = Bs + brr * BSTRIDE + bcc + f * 4;
        pB[0] = f2tf32(pb[f].x); pB[1] = f2tf32(pb[f].y);
        pB[2] = f2tf32(pb[f].z); pB[3] = f2tf32(pb[f].w);
    }
    __syncthreads();

    for (int ks = 0; ks < 256; ks += 32) {
        const bool more = (ks + 32) < 256;
        if (more) {
#pragma unroll
            for (int f = 0; f < 4; ++f) {
                pa[f] = *(const float4*)(w_rep + (m0 + ar) * 256 + ks + 32 + ac + f * 4);
                pb[f] = *(const float4*)(Bbase + (size_t)(ks + 32 + brr) * SPA + s0 + bcc + f * 4);
            }
        }
#pragma unroll
        for (int kk = 0; kk < 32; kk += 8)
            mma_tile_step(As, Bs, mw, nw, g, tig, kk, acc);
        __syncthreads();
        if (more) {
#pragma unroll
            for (int f = 0; f < 4; ++f) {
                uint32_t* pA = As + ar * ASTRIDE + ac + f * 4;
                pA[0] = f2tf32(pa[f].x); pA[1] = f2tf32(pa[f].y);
                pA[2] = f2tf32(pa[f].z); pA[3] = f2tf32(pa[f].w);
                uint32_t* pB = Bs + brr * BSTRIDE + bcc + f * 4;
                pB[0] = f2tf32(pb[f].x); pB[1] = f2tf32(pb[f].y);
                pB[2] = f2tf32(pb[f].z); pB[3] = f2tf32(pb[f].w);
            }
            __syncthreads();
        }
    }

#pragma unroll
    for (int i = 0; i < 4; ++i) {
        int row0 = m0 + mw + i * 16 + g;
        float bias0 = b_rep[row0];
        float bias1 = b_rep[row0 + 8];
#pragma unroll
        for (int j = 0; j < 4; ++j) {
            int col = s0 + nw + j * 8 + tig * 2;
            float* o0 = out + (size_t)(b * CCH + row0) * SPA + col;
            float* o1 = o0 + (size_t)8 * SPA;
            *(float2*)o0 = make_float2(acc[i][j][0] + bias0, acc[i][j][1] + bias0);
            *(float2*)o1 = make_float2(acc[i][j][2] + bias1, acc[i][j][3] + bias1);
        }
    }
}

// ---------------- launch ----------------
extern "C" void kernel_launch(void* const* d_in, const int* in_sizes, int n_in,
                              void* d_out, int out_size) {
    const float* x     = (const float*)d_in[0];
    const float* gamma = (const float*)d_in[1];
    const float* beta  = (const float*)d_in[2];
    const float* wk    = (const float*)d_in[3];
    const float* bk    = (const float*)d_in[4];
    const float* wq    = (const float*)d_in[5];
    const float* bq    = (const float*)d_in[6];
    const float* wv    = (const float*)d_in[7];
    const float* bv    = (const float*)d_in[8];
    const float* w_fc1 = (const float*)d_in[9];
    const float* b_fc1 = (const float*)d_in[10];
    const float* w_fc2 = (const float*)d_in[11];
    const float* b_fc2 = (const float*)d_in[12];
    const float* w_se  = (const float*)d_in[13];
    const float* b_se  = (const float*)d_in[14];
    const float* w_rep = (const float*)d_in[15];
    const float* b_rep = (const float*)d_in[16];
    float* out = (float*)d_out;

    k_bnstats<<<256, 256>>>(x);
    k_fuseW<<<3, 256>>>(wk, bk, wq, bq, wv, bv, gamma, beta);
    k_gemm_kqv<<<dim3(1024, 6), 256>>>(x);
    k_ksoftmax<<<2048, 256>>>();
    k_qsoftmax<<<1024, 256>>>();
    k_context<<<dim3(16, 16), 256>>>();
    k_reduce_ctx<<<16, 256>>>();
    k_gate<<<1, 32>>>(w_fc1, b_fc1, w_fc2, b_fc2);
    k_combine<<<512, 256>>>(w_se, b_se);
    k_attn2<<<dim3(128, 16), 256>>>();
    k_final<<<dim3(1024, 2), 256>>>(w_rep, b_rep, out);
}

// round 3
// speedup vs baseline: 1.9822x; 1.0084x over previous
#include <cuda_runtime.h>
#include <cuda_bf16.h>
#include <cstdint>

#define BATCH 8
#define CCH   256
#define SPA   16384
#define HEADS 2
#define HK    128

// ---------------- scratch ----------------
__device__ float g_mean[CCH];
__device__ float g_rstd[CCH];
__device__ float g_wf[768 * 256];
__device__ float g_bf[768];
__device__ float g_k[BATCH * CCH * SPA];
__device__ float g_q[BATCH * CCH * SPA];
__device__ float g_v[BATCH * CCH * SPA];
__device__ float g_ctx_part[16 * 16 * 128 * 128];
__device__ float g_context[16 * 128 * 128];
__device__ float g_ctx[BATCH * 128 * 128];
__device__ float g_pooled[16];
__device__ float g_gate[16];
__device__ float g_kmax[2048];          // per (b,n,kc) row of k
__device__ float g_kinv[2048];
__device__ float g_qm[BATCH * 2 * SPA]; // per (b,n,s) column of q
__device__ float g_qinv[BATCH * 2 * SPA];
__device__ float g_M[BATCH * 256 * 256];
__device__ float g_b2[256];

// ---------------- tf32 mma helpers ----------------
__device__ __forceinline__ uint32_t f2tf32(float f) {
    uint32_t r;
    asm("cvt.rna.tf32.f32 %0, %1;" : "=r"(r) : "f"(f));
    return r;
}

__device__ __forceinline__ void mma_tf32(float c[4], const uint32_t a[4], const uint32_t b[2]) {
    asm volatile(
        "mma.sync.aligned.m16n8k8.row.col.f32.tf32.tf32.f32 "
        "{%0,%1,%2,%3}, {%4,%5,%6,%7}, {%8,%9}, {%0,%1,%2,%3};"
        : "+f"(c[0]), "+f"(c[1]), "+f"(c[2]), "+f"(c[3])
        : "r"(a[0]), "r"(a[1]), "r"(a[2]), "r"(a[3]), "r"(b[0]), "r"(b[1]));
}

#define ASTRIDE 36
#define BSTRIDE 132

__device__ __forceinline__ void mma_tile_step(
    const uint32_t* __restrict__ As, const uint32_t* __restrict__ Bs,
    int mw, int nw, int g, int tig, int kk, float (&acc)[4][4][4])
{
    uint32_t a[4][4], b[4][2];
#pragma unroll
    for (int i = 0; i < 4; ++i) {
        const uint32_t* A0 = As + (mw + i * 16 + g) * ASTRIDE + kk;
        const uint32_t* A1 = A0 + 8 * ASTRIDE;
        a[i][0] = A0[tig];     a[i][1] = A1[tig];
        a[i][2] = A0[tig + 4]; a[i][3] = A1[tig + 4];
    }
#pragma unroll
    for (int j = 0; j < 4; ++j) {
        int cb = nw + j * 8 + g;
        b[j][0] = Bs[(kk + tig) * BSTRIDE + cb];
        b[j][1] = Bs[(kk + tig + 4) * BSTRIDE + cb];
    }
#pragma unroll
    for (int i = 0; i < 4; ++i)
#pragma unroll
        for (int j = 0; j < 4; ++j)
            mma_tf32(acc[i][j], a[i], b[j]);
}

// ---------------- K1: BatchNorm statistics ----------------
__global__ void k_bnstats(const float* __restrict__ x) {
    const int c = blockIdx.x;
    const int tid = threadIdx.x;
    float s = 0.f, s2 = 0.f;
    for (int b = 0; b < BATCH; ++b) {
        const float4* p = (const float4*)(x + ((size_t)(b * CCH + c) << 14));
        for (int i = tid; i < SPA / 4; i += 256) {
            float4 v = p[i];
            s  += v.x + v.y + v.z + v.w;
            s2 += v.x * v.x + v.y * v.y + v.z * v.z + v.w * v.w;
        }
    }
    __shared__ float sa[256], sb[256];
    sa[tid] = s; sb[tid] = s2;
    __syncthreads();
    for (int st = 128; st > 0; st >>= 1) {
        if (tid < st) { sa[tid] += sa[tid + st]; sb[tid] += sb[tid + st]; }
        __syncthreads();
    }
    if (tid == 0) {
        const float inv_n = 1.f / (float)(BATCH * SPA);
        float mean = sa[0] * inv_n;
        float var  = sb[0] * inv_n - mean * mean;
        g_mean[c] = mean;
        g_rstd[c] = rsqrtf(var + 1e-5f);
    }
}

// ---------------- K2: fold BN into kqv weights ----------------
__global__ void k_fuseW(const float* __restrict__ wk, const float* __restrict__ bk,
                        const float* __restrict__ wq, const float* __restrict__ bq,
                        const float* __restrict__ wv, const float* __restrict__ bv,
                        const float* __restrict__ gamma, const float* __restrict__ beta) {
    int o = blockIdx.x * blockDim.x + threadIdx.x;
    if (o >= 768) return;
    const float* W; const float* bias; int r;
    if (o < 256)      { W = wk; bias = bk; r = o; }
    else if (o < 512) { W = wq; bias = bq; r = o - 256; }
    else              { W = wv; bias = bv; r = o - 512; }
    float bacc = bias[r];
    for (int c = 0; c < 256; ++c) {
        float a = g_rstd[c] * gamma[c];
        float d = beta[c] - g_mean[c] * a;
        float w = W[r * 256 + c];
        g_wf[o * 256 + c] = w * a;
        bacc += w * d;
    }
    g_bf[o] = bacc;
}

// ---------------- K3: fused kqv GEMM (tf32), m-tile on blockIdx.x for L2 reuse ----
__global__ __launch_bounds__(256) void k_gemm_kqv(const float* __restrict__ x) {
    __shared__ uint32_t As[128 * ASTRIDE];
    __shared__ uint32_t Bs[32 * BSTRIDE];
    const int tid = threadIdx.x;
    const int lane = tid & 31;
    const int wid = tid >> 5;
    const int g = lane >> 2, tig = lane & 3;
    const int mw = (wid & 1) * 64, nw = (wid >> 1) * 32;

    const int m0 = blockIdx.x << 7;        // 0..5 m-tiles (fast dim -> L2 reuse of x)
    const int by = blockIdx.y;             // 0..1023 (b, s-tile)
    const int b  = by >> 7;
    const int s0 = (by & 127) << 7;
    const float* Bbase = x + ((size_t)b * CCH) * SPA;

    const int ar = tid >> 1;
    const int ac = (tid & 1) << 4;
    const int brr = tid >> 3;
    const int bcc = (tid & 7) << 4;

    float acc[4][4][4] = {};
    float4 pa[4], pb[4];

#pragma unroll
    for (int f = 0; f < 4; ++f) {
        pa[f] = *(const float4*)(g_wf + (m0 + ar) * 256 + ac + f * 4);
        pb[f] = *(const float4*)(Bbase + (size_t)brr * SPA + s0 + bcc + f * 4);
    }
#pragma unroll
    for (int f = 0; f < 4; ++f) {
        uint32_t* pA = As + ar * ASTRIDE + ac + f * 4;
        pA[0] = f2tf32(pa[f].x); pA[1] = f2tf32(pa[f].y);
        pA[2] = f2tf32(pa[f].z); pA[3] = f2tf32(pa[f].w);
        uint32_t* pB = Bs + brr * BSTRIDE + bcc + f * 4;
        pB[0] = f2tf32(pb[f].x); pB[1] = f2tf32(pb[f].y);
        pB[2] = f2tf32(pb[f].z); pB[3] = f2tf32(pb[f].w);
    }
    __syncthreads();

    for (int ks = 0; ks < 256; ks += 32) {
        const bool more = (ks + 32) < 256;
        if (more) {
#pragma unroll
            for (int f = 0; f < 4; ++f) {
                pa[f] = *(const float4*)(g_wf + (m0 + ar) * 256 + ks + 32 + ac + f * 4);
                pb[f] = *(const float4*)(Bbase + (size_t)(ks + 32 + brr) * SPA + s0 + bcc + f * 4);
            }
        }
#pragma unroll
        for (int kk = 0; kk < 32; kk += 8)
            mma_tile_step(As, Bs, mw, nw, g, tig, kk, acc);
        __syncthreads();
        if (more) {
#pragma unroll
            for (int f = 0; f < 4; ++f) {
                uint32_t* pA = As + ar * ASTRIDE + ac + f * 4;
                pA[0] = f2tf32(pa[f].x); pA[1] = f2tf32(pa[f].y);
                pA[2] = f2tf32(pa[f].z); pA[3] = f2tf32(pa[f].w);
                uint32_t* pB = Bs + brr * BSTRIDE + bcc + f * 4;
                pB[0] = f2tf32(pb[f].x); pB[1] = f2tf32(pb[f].y);
                pB[2] = f2tf32(pb[f].z); pB[3] = f2tf32(pb[f].w);
            }
            __syncthreads();
        }
    }

    float* dst; int rbase;
    if (m0 < 256)      { dst = g_k; rbase = m0; }
    else if (m0 < 512) { dst = g_q; rbase = m0 - 256; }
    else               { dst = g_v; rbase = m0 - 512; }

#pragma unroll
    for (int i = 0; i < 4; ++i) {
        int row0 = mw + i * 16 + g;
        float bias0 = g_bf[m0 + row0];
        float bias1 = g_bf[m0 + row0 + 8];
#pragma unroll
        for (int j = 0; j < 4; ++j) {
            int col = s0 + nw + j * 8 + tig * 2;
            float* o0 = dst + (size_t)(b * CCH + rbase + row0) * SPA + col;
            float* o1 = o0 + 8 * SPA;
            *(float2*)o0 = make_float2(acc[i][j][0] + bias0, acc[i][j][1] + bias0);
            *(float2*)o1 = make_float2(acc[i][j][2] + bias1, acc[i][j][3] + bias1);
        }
    }
}

// ---------------- K4: k row stats (max, 1/sumexp) — no write-back ----------------
__global__ __launch_bounds__(256) void k_kstats() {
    const size_t base = (size_t)blockIdx.x << 14;
    const float4* p = (const float4*)(g_k + base);
    const int tid = threadIdx.x;
    float4 v[16];
    float m = -1e30f;
#pragma unroll
    for (int i = 0; i < 16; ++i) {
        v[i] = p[tid + (i << 8)];
        m = fmaxf(m, fmaxf(fmaxf(v[i].x, v[i].y), fmaxf(v[i].z, v[i].w)));
    }
    __shared__ float sm[256];
    sm[tid] = m; __syncthreads();
    for (int st = 128; st > 0; st >>= 1) {
        if (tid < st) sm[tid] = fmaxf(sm[tid], sm[tid + st]);
        __syncthreads();
    }
    const float rowm = sm[0];
    __syncthreads();
    float l = 0.f;
#pragma unroll
    for (int i = 0; i < 16; ++i)
        l += __expf(v[i].x - rowm) + __expf(v[i].y - rowm)
           + __expf(v[i].z - rowm) + __expf(v[i].w - rowm);
    sm[tid] = l; __syncthreads();
    for (int st = 128; st > 0; st >>= 1) {
        if (tid < st) sm[tid] += sm[tid + st];
        __syncthreads();
    }
    if (tid == 0) {
        g_kmax[blockIdx.x] = rowm;
        g_kinv[blockIdx.x] = 1.f / sm[0];
    }
}

// ---------------- K5: q column stats (max, 1/sumexp) over 128 channels -----------
__global__ void k_qstats() {
    int j = blockIdx.x * 256 + threadIdx.x;    // 0..262143
    int b = j >> 15;
    int n = (j >> 14) & 1;
    int s = j & 16383;
    const float* col = g_q + ((size_t)(b * CCH + n * HK)) * SPA + s;
    float m = -1e30f, l = 0.f;
    for (int kc = 0; kc < HK; ++kc) {
        float xv = col[(size_t)kc * SPA];
        float nm = fmaxf(m, xv);
        l = l * __expf(m - nm) + __expf(xv - nm);
        m = nm;
    }
    g_qm[j]   = m;
    g_qinv[j] = 1.f / l;
}

// ---------------- K6: context partials softmax(k) @ v^T (exp fused in staging) ---
__global__ __launch_bounds__(256) void k_context() {
    __shared__ uint32_t As[128 * ASTRIDE];
    __shared__ uint32_t Bs[32 * BSTRIDE];
    const int tid = threadIdx.x;
    const int lane = tid & 31;
    const int wid = tid >> 5;
    const int g = lane >> 2, tig = lane & 3;
    const int mw = (wid & 1) * 64, nw = (wid >> 1) * 32;

    const int split = blockIdx.x;
    const int bn = blockIdx.y;
    const float* Kb = g_k + ((size_t)bn * HK) * SPA;
    const float* Vb = g_v + ((size_t)bn * HK) * SPA;
    const int sb0 = split * 1024;

    const int ar = tid >> 1;
    const int ac = (tid & 1) << 4;
    const int vr = tid >> 1;
    const int vq = (tid & 1) << 4;

    const float km  = g_kmax[bn * HK + ar];
    const float kiv = g_kinv[bn * HK + ar];

    float acc[4][4][4] = {};
    float4 pa[4], pb[4];

#pragma unroll
    for (int f = 0; f < 4; ++f) {
        pa[f] = *(const float4*)(Kb + (size_t)ar * SPA + sb0 + ac + f * 4);
        pb[f] = *(const float4*)(Vb + (size_t)vr * SPA + sb0 + vq + f * 4);
    }
#pragma unroll
    for (int f = 0; f < 4; ++f) {
        uint32_t* pA = As + ar * ASTRIDE + ac + f * 4;
        pA[0] = f2tf32(__expf(pa[f].x - km) * kiv);
        pA[1] = f2tf32(__expf(pa[f].y - km) * kiv);
        pA[2] = f2tf32(__expf(pa[f].z - km) * kiv);
        pA[3] = f2tf32(__expf(pa[f].w - km) * kiv);
        int sbase = vq + f * 4;
        Bs[(sbase + 0) * BSTRIDE + vr] = f2tf32(pb[f].x);
        Bs[(sbase + 1) * BSTRIDE + vr] = f2tf32(pb[f].y);
        Bs[(sbase + 2) * BSTRIDE + vr] = f2tf32(pb[f].z);
        Bs[(sbase + 3) * BSTRIDE + vr] = f2tf32(pb[f].w);
    }
    __syncthreads();

    for (int ks = 0; ks < 1024; ks += 32) {
        const bool more = (ks + 32) < 1024;
        if (more) {
#pragma unroll
            for (int f = 0; f < 4; ++f) {
                pa[f] = *(const float4*)(Kb + (size_t)ar * SPA + sb0 + ks + 32 + ac + f * 4);
                pb[f] = *(const float4*)(Vb + (size_t)vr * SPA + sb0 + ks + 32 + vq + f * 4);
            }
        }
#pragma unroll
        for (int kk = 0; kk < 32; kk += 8)
            mma_tile_step(As, Bs, mw, nw, g, tig, kk, acc);
        __syncthreads();
        if (more) {
#pragma unroll
            for (int f = 0; f < 4; ++f) {
                uint32_t* pA = As + ar * ASTRIDE + ac + f * 4;
                pA[0] = f2tf32(__expf(pa[f].x - km) * kiv);
                pA[1] = f2tf32(__expf(pa[f].y - km) * kiv);
                pA[2] = f2tf32(__expf(pa[f].z - km) * kiv);
                pA[3] = f2tf32(__expf(pa[f].w - km) * kiv);
                int sbase = vq + f * 4;
                Bs[(sbase + 0) * BSTRIDE + vr] = f2tf32(pb[f].x);
                Bs[(sbase + 1) * BSTRIDE + vr] = f2tf32(pb[f].y);
                Bs[(sbase + 2) * BSTRIDE + vr] = f2tf32(pb[f].z);
                Bs[(sbase + 3) * BSTRIDE + vr] = f2tf32(pb[f].w);
            }
            __syncthreads();
        }
    }

    float* outp = g_ctx_part + ((size_t)(bn * 16 + split)) * 16384;
#pragma unroll
    for (int i = 0; i < 4; ++i) {
        int row0 = mw + i * 16 + g;
#pragma unroll
        for (int j = 0; j < 4; ++j) {
            int col = nw + j * 8 + tig * 2;
            float* o0 = outp + row0 * 128 + col;
            float* o1 = o0 + 8 * 128;
            *(float2*)o0 = make_float2(acc[i][j][0], acc[i][j][1]);
            *(float2*)o1 = make_float2(acc[i][j][2], acc[i][j][3]);
        }
    }
}

// ---------------- K7: reduce partials + pooled mean ----------------
__global__ void k_reduce_ctx() {
    const int bn = blockIdx.x;
    const int tid = threadIdx.x;
    float acc = 0.f;
    for (int e = tid; e < 16384; e += 256) {
        float s = 0.f;
#pragma unroll
        for (int p = 0; p < 16; ++p)
            s += g_ctx_part[((size_t)(bn * 16 + p)) * 16384 + e];
        g_context[((size_t)bn << 14) + e] = s;
        acc += s;
    }
    __shared__ float sm[256];
    sm[tid] = acc; __syncthreads();
    for (int st = 128; st > 0; st >>= 1) {
        if (tid < st) sm[tid] += sm[tid + st];
        __syncthreads();
    }
    if (tid == 0) g_pooled[bn] = sm[0] * (1.f / 16384.f);
}

// ---------------- K8: SE gate ----------------
__global__ void k_gate(const float* __restrict__ w_fc1, const float* __restrict__ b_fc1,
                       const float* __restrict__ w_fc2, const float* __restrict__ b_fc2) {
    int b = threadIdx.x;
    if (b >= BATCH) return;
    float p0 = g_pooled[b * 2], p1 = g_pooled[b * 2 + 1];
    float h0 = fmaxf(0.f, p0 * w_fc1[0] + p1 * w_fc1[1] + b_fc1[0]);
    float h1 = fmaxf(0.f, p0 * w_fc1[2] + p1 * w_fc1[3] + b_fc1[1]);
    float z0 = h0 * w_fc2[0] + h1 * w_fc2[1] + b_fc2[0];
    float z1 = h0 * w_fc2[2] + h1 * w_fc2[3] + b_fc2[1];
    g_gate[b * 2]     = 1.f / (1.f + __expf(-z0));
    g_gate[b * 2 + 1] = 1.f / (1.f + __expf(-z1));
}

// ---------------- K9: combine heads (gated, NO b_se — folded into bias) ----------
__global__ void k_combine(const float* __restrict__ w_se) {
    int idx = blockIdx.x * 256 + threadIdx.x;
    int b = idx >> 14;
    int e = idx & 16383;
    float v = w_se[0] * g_gate[b * 2]     * g_context[((size_t)(b * 2))     * 16384 + e]
            + w_se[1] * g_gate[b * 2 + 1] * g_context[((size_t)(b * 2 + 1)) * 16384 + e];
    g_ctx[idx] = v;
}

// ---------------- K10: M_b[o, n*128+kc] = sum_vc w_rep[o, n*128+vc] * ctx_b[kc,vc] -
__global__ __launch_bounds__(256) void k_mkM(const float* __restrict__ w_rep) {
    __shared__ float Ws[64][65];
    __shared__ float Cs[64][65];
    const int bid = blockIdx.x;           // 128 blocks
    const int b = bid >> 4;
    const int rem = bid & 15;
    const int ot = rem >> 2, kt = rem & 3;
    const int n = kt >> 1;
    const int kc0 = (kt & 1) << 6;
    const int o0 = ot << 6;
    const int tid = threadIdx.x;
    const int tx = tid & 15, ty = tid >> 4;
    const float* ctxb = g_ctx + (size_t)b * 16384;
    float acc[4][4] = {};
    const int lrow = tid >> 2;
    const int lc0 = (tid & 3) << 4;
    for (int h = 0; h < 2; ++h) {
        const int vb = n * 128 + h * 64;
#pragma unroll
        for (int f = 0; f < 4; ++f) {
            float4 wv = *(const float4*)(w_rep + (o0 + lrow) * 256 + vb + lc0 + f * 4);
            Ws[lrow][lc0 + f * 4 + 0] = wv.x; Ws[lrow][lc0 + f * 4 + 1] = wv.y;
            Ws[lrow][lc0 + f * 4 + 2] = wv.z; Ws[lrow][lc0 + f * 4 + 3] = wv.w;
            float4 cv = *(const float4*)(ctxb + (kc0 + lrow) * 128 + h * 64 + lc0 + f * 4);
            Cs[lrow][lc0 + f * 4 + 0] = cv.x; Cs[lrow][lc0 + f * 4 + 1] = cv.y;
            Cs[lrow][lc0 + f * 4 + 2] = cv.z; Cs[lrow][lc0 + f * 4 + 3] = cv.w;
        }
        __syncthreads();
        for (int vl = 0; vl < 64; ++vl) {
            float a[4], bb[4];
#pragma unroll
            for (int i = 0; i < 4; ++i) a[i]  = Ws[ty * 4 + i][vl];
#pragma unroll
            for (int j = 0; j < 4; ++j) bb[j] = Cs[tx * 4 + j][vl];
#pragma unroll
            for (int i = 0; i < 4; ++i)
#pragma unroll
                for (int j = 0; j < 4; ++j) acc[i][j] += a[i] * bb[j];
        }
        __syncthreads();
    }
#pragma unroll
    for (int i = 0; i < 4; ++i)
#pragma unroll
        for (int j = 0; j < 4; ++j)
            g_M[(size_t)b * 65536 + (o0 + ty * 4 + i) * 256 + kt * 64 + tx * 4 + j] = acc[i][j];
}

// ---------------- K11: b2[o] = b_rep[o] + b_se * sum_c w_rep[o,c] -----------------
__global__ void k_bias2(const float* __restrict__ w_rep, const float* __restrict__ b_rep,
                        const float* __restrict__ b_se) {
    int o = threadIdx.x;
    float s = 0.f;
    for (int c = 0; c < 256; ++c) s += w_rep[o * 256 + c];
    g_b2[o] = b_rep[o] + b_se[0] * s;
}

// ---------------- K12: fused final GEMM  M_b @ softmax_q + b2 (exp fused) --------
__global__ __launch_bounds__(256) void k_final_fused(float* __restrict__ out) {
    __shared__ uint32_t As[128 * ASTRIDE];
    __shared__ uint32_t Bs[32 * BSTRIDE];
    const int tid = threadIdx.x;
    const int lane = tid & 31;
    const int wid = tid >> 5;
    const int g = lane >> 2, tig = lane & 3;
    const int mw = (wid & 1) * 64, nw = (wid >> 1) * 32;

    const int m0 = blockIdx.x << 7;        // 0 or 128 (fast dim -> L2 reuse of q)
    const int by = blockIdx.y;             // 0..1023
    const int b  = by >> 7;
    const int s0 = (by & 127) << 7;
    const float* Am = g_M + (size_t)b * 65536;
    const float* Bq = g_q + (size_t)b * CCH * SPA;
    const float* qm = g_qm   + ((size_t)(b * 2) << 14);
    const float* qi = g_qinv + ((size_t)(b * 2) << 14);

    const int ar = tid >> 1;
    const int ac = (tid & 1) << 4;
    const int brr = tid >> 3;
    const int bcc = (tid & 7) << 4;

    float acc[4][4][4] = {};
    float4 pa[4], pb[4];

#pragma unroll
    for (int f = 0; f < 4; ++f) {
        pa[f] = *(const float4*)(Am + (m0 + ar) * 256 + ac + f * 4);
        pb[f] = *(const float4*)(Bq + (size_t)brr * SPA + s0 + bcc + f * 4);
    }
    {
        const int nb = 0;   // ks=0 rows are head 0
#pragma unroll
        for (int f = 0; f < 4; ++f) {
            uint32_t* pA = As + ar * ASTRIDE + ac + f * 4;
            pA[0] = f2tf32(pa[f].x); pA[1] = f2tf32(pa[f].y);
            pA[2] = f2tf32(pa[f].z); pA[3] = f2tf32(pa[f].w);
            float4 mv = *(const float4*)(qm + nb + s0 + bcc + f * 4);
            float4 iv = *(const float4*)(qi + nb + s0 + bcc + f * 4);
            uint32_t* pB = Bs + brr * BSTRIDE + bcc + f * 4;
            pB[0] = f2tf32(__expf(pb[f].x - mv.x) * iv.x);
            pB[1] = f2tf32(__expf(pb[f].y - mv.y) * iv.y);
            pB[2] = f2tf32(__expf(pb[f].z - mv.z) * iv.z);
            pB[3] = f2tf32(__expf(pb[f].w - mv.w) * iv.w);
        }
    }
    __syncthreads();

    for (int ks = 0; ks < 256; ks += 32) {
        const bool more = (ks + 32) < 256;
        if (more) {
#pragma unroll
            for (int f = 0; f < 4; ++f) {
                pa[f] = *(const float4*)(Am + (m0 + ar) * 256 + ks + 32 + ac + f * 4);
                pb[f] = *(const float4*)(Bq + (size_t)(ks + 32 + brr) * SPA + s0 + bcc + f * 4);
            }
        }
#pragma unroll
        for (int kk = 0; kk < 32; kk += 8)
            mma_tile_step(As, Bs, mw, nw, g, tig, kk, acc);
        __syncthreads();
        if (more) {
            const int nb = (((ks + 32) >> 7) << 14);   // head select for these rows
#pragma unroll
            for (int f = 0; f < 4; ++f) {
                uint32_t* pA = As + ar * ASTRIDE + ac + f * 4;
                pA[0] = f2tf32(pa[f].x); pA[1] = f2tf32(pa[f].y);
                pA[2] = f2tf32(pa[f].z); pA[3] = f2tf32(pa[f].w);
                float4 mv = *(const float4*)(qm + nb + s0 + bcc + f * 4);
                float4 iv = *(const float4*)(qi + nb + s0 + bcc + f * 4);
                uint32_t* pB = Bs + brr * BSTRIDE + bcc + f * 4;
                pB[0] = f2tf32(__expf(pb[f].x - mv.x) * iv.x);
                pB[1] = f2tf32(__expf(pb[f].y - mv.y) * iv.y);
                pB[2] = f2tf32(__expf(pb[f].z - mv.z) * iv.z);
                pB[3] = f2tf32(__expf(pb[f].w - mv.w) * iv.w);
            }
            __syncthreads();
        }
    }

#pragma unroll
    for (int i = 0; i < 4; ++i) {
        int row0 = m0 + mw + i * 16 + g;
        float bias0 = g_b2[row0];
        float bias1 = g_b2[row0 + 8];
#pragma unroll
        for (int j = 0; j < 4; ++j) {
            int col = s0 + nw + j * 8 + tig * 2;
            float* o0 = out + (size_t)(b * CCH + row0) * SPA + col;
            float* o1 = o0 + (size_t)8 * SPA;
            *(float2*)o0 = make_float2(acc[i][j][0] + bias0, acc[i][j][1] + bias0);
            *(float2*)o1 = make_float2(acc[i][j][2] + bias1, acc[i][j][3] + bias1);
        }
    }
}

// ---------------- launch ----------------
extern "C" void kernel_launch(void* const* d_in, const int* in_sizes, int n_in,
                              void* d_out, int out_size) {
    const float* x     = (const float*)d_in[0];
    const float* gamma = (const float*)d_in[1];
    const float* beta  = (const float*)d_in[2];
    const float* wk    = (const float*)d_in[3];
    const float* bk    = (const float*)d_in[4];
    const float* wq    = (const float*)d_in[5];
    const float* bq    = (const float*)d_in[6];
    const float* wv    = (const float*)d_in[7];
    const float* bv    = (const float*)d_in[8];
    const float* w_fc1 = (const float*)d_in[9];
    const float* b_fc1 = (const float*)d_in[10];
    const float* w_fc2 = (const float*)d_in[11];
    const float* b_fc2 = (const float*)d_in[12];
    const float* w_se  = (const float*)d_in[13];
    const float* b_se  = (const float*)d_in[14];
    const float* w_rep = (const float*)d_in[15];
    const float* b_rep = (const float*)d_in[16];
    float* out = (float*)d_out;

    k_bnstats<<<256, 256>>>(x);
    k_fuseW<<<3, 256>>>(wk, bk, wq, bq, wv, bv, gamma, beta);
    k_gemm_kqv<<<dim3(6, 1024), 256>>>(x);
    k_kstats<<<2048, 256>>>();
    k_qstats<<<1024, 256>>>();
    k_context<<<dim3(16, 16), 256>>>();
    k_reduce_ctx<<<16, 256>>>();
    k_gate<<<1, 32>>>(w_fc1, b_fc1, w_fc2, b_fc2);
    k_combine<<<512, 256>>>(w_se);
    k_mkM<<<128, 256>>>(w_rep);
    k_bias2<<<1, 256>>>(w_rep, b_rep, b_se);
    k_final_fused<<<dim3(2, 1024), 256>>>(out);
}